// round 1
// baseline (speedup 1.0000x reference)
#include <cuda_runtime.h>
#include <cuda_bf16.h>
#include <stdint.h>

#define NN   100000
#define NE   1600000
#define INF  256
#define OUTF 64

// ---------------- scratch (device globals; no allocations allowed) ----------
__device__ int   g_deg[NN];
__device__ int   g_rowptr[NN + 1];
__device__ int   g_cursor[NN];
__device__ int   g_csr_src[NE];
__device__ float g_csr_w[NE];
__device__ float g_WT[INF * OUTF];          // W^T  [k][c]
__device__ float g_buf0[(size_t)NN * OUTF];
__device__ float g_buf1[(size_t)NN * OUTF];

// ---------------- CSR build --------------------------------------------------
__global__ void k_zero_deg() {
    int i = blockIdx.x * blockDim.x + threadIdx.x;
    if (i < NN) g_deg[i] = 0;
}

__global__ void k_hist(const int* __restrict__ dst, int E) {
    int e = blockIdx.x * blockDim.x + threadIdx.x;
    if (e < E) atomicAdd(&g_deg[dst[e]], 1);
}

// single-block exclusive scan of g_deg -> g_rowptr / g_cursor
__global__ void k_scan() {
    __shared__ int sums[1024];
    const int t  = threadIdx.x;
    const int CH = (NN + 1023) / 1024;
    int beg = t * CH;
    int end = beg + CH; if (end > NN) end = NN;
    if (beg > NN) beg = NN;

    int s = 0;
    for (int i = beg; i < end; ++i) s += g_deg[i];
    sums[t] = s;
    __syncthreads();
    // Kogge-Stone inclusive scan over 1024 partials
    for (int off = 1; off < 1024; off <<= 1) {
        int v = (t >= off) ? sums[t - off] : 0;
        __syncthreads();
        sums[t] += v;
        __syncthreads();
    }
    int pre = (t == 0) ? 0 : sums[t - 1];
    for (int i = beg; i < end; ++i) {
        g_rowptr[i] = pre;
        g_cursor[i] = pre;
        pre += g_deg[i];
    }
    if (t == 1023) g_rowptr[NN] = pre;
}

__global__ void k_scatter(const int* __restrict__ src, const int* __restrict__ dst,
                          const float* __restrict__ w, int E) {
    int e = blockIdx.x * blockDim.x + threadIdx.x;
    if (e < E) {
        int d = dst[e];
        int p = atomicAdd(&g_cursor[d], 1);
        g_csr_src[p] = src[e];
        g_csr_w[p]   = w[e];
    }
}

// ---------------- W transpose ------------------------------------------------
__global__ void k_transpose_w(const float* __restrict__ W) {
    int i = blockIdx.x * blockDim.x + threadIdx.x;   // i = c*256 + k
    if (i < OUTF * INF) {
        int c = i >> 8;
        int k = i & 255;
        g_WT[k * OUTF + c] = W[i];
    }
}

// ---------------- GEMM: out = x @ W^T + b  ->  g_buf0 ------------------------
// block: 128 threads, tile 64 rows x 64 cols, thread tile 4x8
__global__ void k_gemm(const float* __restrict__ x, const float* __restrict__ bias, int M) {
    __shared__ float xs[64 * 64];   // [row][k]
    __shared__ float ws[64 * 64];   // [k][c]
    const int t  = threadIdx.x;
    const int tx = t & 7;           // col group: cols tx*8 .. tx*8+7
    const int ty = t >> 3;          // row group: rows ty*4 .. ty*4+3
    const int m0 = blockIdx.x * 64;

    float acc[4][8];
#pragma unroll
    for (int j = 0; j < 4; ++j)
#pragma unroll
        for (int jj = 0; jj < 8; ++jj) acc[j][jj] = 0.f;

    for (int kb = 0; kb < INF; kb += 64) {
#pragma unroll
        for (int i = 0; i < 8; ++i) {
            int idx = i * 128 + t;       // 0..1023 float4 slots
            int row = idx >> 4;          // 0..63
            int kq  = idx & 15;          // 0..15 (float4 within 64)
            float4 v = make_float4(0.f, 0.f, 0.f, 0.f);
            if (m0 + row < M)
                v = *(const float4*)&x[(size_t)(m0 + row) * INF + kb + kq * 4];
            *(float4*)&xs[row * 64 + kq * 4] = v;
            // ws: idx reinterpreted as k(=row), col-quad(=kq); g_WT is [k][c]
            float4 wv = *(const float4*)&g_WT[(kb + row) * OUTF + kq * 4];
            *(float4*)&ws[row * 64 + kq * 4] = wv;
        }
        __syncthreads();
#pragma unroll
        for (int k = 0; k < 64; ++k) {
            float4 b0 = *(const float4*)&ws[k * 64 + tx * 8];
            float4 b1 = *(const float4*)&ws[k * 64 + tx * 8 + 4];
            float a[4];
#pragma unroll
            for (int j = 0; j < 4; ++j) a[j] = xs[(ty * 4 + j) * 64 + k];
#pragma unroll
            for (int j = 0; j < 4; ++j) {
                acc[j][0] += a[j] * b0.x; acc[j][1] += a[j] * b0.y;
                acc[j][2] += a[j] * b0.z; acc[j][3] += a[j] * b0.w;
                acc[j][4] += a[j] * b1.x; acc[j][5] += a[j] * b1.y;
                acc[j][6] += a[j] * b1.z; acc[j][7] += a[j] * b1.w;
            }
        }
        __syncthreads();
    }

    float4 bb0 = *(const float4*)&bias[tx * 8];
    float4 bb1 = *(const float4*)&bias[tx * 8 + 4];
#pragma unroll
    for (int j = 0; j < 4; ++j) {
        int row = m0 + ty * 4 + j;
        if (row < M) {
            float4 o0 = make_float4(acc[j][0] + bb0.x, acc[j][1] + bb0.y,
                                    acc[j][2] + bb0.z, acc[j][3] + bb0.w);
            float4 o1 = make_float4(acc[j][4] + bb1.x, acc[j][5] + bb1.y,
                                    acc[j][6] + bb1.z, acc[j][7] + bb1.w);
            *(float4*)&g_buf0[(size_t)row * OUTF + tx * 8]     = o0;
            *(float4*)&g_buf0[(size_t)row * OUTF + tx * 8 + 4] = o1;
        }
    }
}

// ---------------- SpMM hop (CSR gather, no float atomics) --------------------
// blockDim = (32, 8): one warp per node, lane f handles features 2f, 2f+1
__global__ void k_spmm(int insel, int outsel, float* __restrict__ dout) {
    const float2* __restrict__ in =
        (insel == 0) ? (const float2*)g_buf0 : (const float2*)g_buf1;
    float2* __restrict__ out =
        (outsel == 0) ? (float2*)g_buf0 :
        (outsel == 1) ? (float2*)g_buf1 : (float2*)dout;

    int node = blockIdx.x * 8 + threadIdx.y;
    if (node >= NN) return;
    int f = threadIdx.x;                  // 0..31
    int beg = g_rowptr[node];
    int end = g_rowptr[node + 1];

    float2 acc = make_float2(0.f, 0.f);
    int e = beg;
    for (; e + 2 <= end; e += 2) {
        int   s0 = __ldg(&g_csr_src[e]);
        int   s1 = __ldg(&g_csr_src[e + 1]);
        float w0 = __ldg(&g_csr_w[e]);
        float w1 = __ldg(&g_csr_w[e + 1]);
        float2 v0 = __ldg(&in[(size_t)s0 * 32 + f]);
        float2 v1 = __ldg(&in[(size_t)s1 * 32 + f]);
        acc.x += w0 * v0.x; acc.y += w0 * v0.y;
        acc.x += w1 * v1.x; acc.y += w1 * v1.y;
    }
    if (e < end) {
        int   s = __ldg(&g_csr_src[e]);
        float w = __ldg(&g_csr_w[e]);
        float2 v = __ldg(&in[(size_t)s * 32 + f]);
        acc.x += w * v.x; acc.y += w * v.y;
    }
    out[(size_t)node * 32 + f] = acc;
}

// ---------------- launch -----------------------------------------------------
extern "C" void kernel_launch(void* const* d_in, const int* in_sizes, int n_in,
                              void* d_out, int out_size) {
    const float* x    = (const float*)d_in[0];
    const float* W    = (const float*)d_in[1];
    const float* bias = (const float*)d_in[2];
    const int*   esrc = (const int*)d_in[3];
    const int*   edst = (const int*)d_in[4];
    const float* ew   = (const float*)d_in[5];
    float* out = (float*)d_out;

    const int M = in_sizes[0] / INF;      // 100000
    const int E = in_sizes[3];            // 1600000

    // W^T
    k_transpose_w<<<(OUTF * INF + 255) / 256, 256>>>(W);
    // CSR build (by dst)
    k_zero_deg<<<(NN + 255) / 256, 256>>>();
    k_hist<<<(E + 255) / 256, 256>>>(edst, E);
    k_scan<<<1, 1024>>>();
    k_scatter<<<(E + 255) / 256, 256>>>(esrc, edst, ew, E);
    // GEMM -> buf0
    k_gemm<<<(M + 63) / 64, 128>>>(x, bias, M);
    // 3 hops: buf0 -> buf1 -> buf0 -> d_out
    dim3 bt(32, 8);
    int nblk = (NN + 7) / 8;
    k_spmm<<<nblk, bt>>>(0, 1, out);
    k_spmm<<<nblk, bt>>>(1, 0, out);
    k_spmm<<<nblk, bt>>>(0, 2, out);
    (void)n_in; (void)out_size;
}

// round 4
// speedup vs baseline: 1.4595x; 1.4595x over previous
#include <cuda_runtime.h>
#include <cuda_bf16.h>
#include <stdint.h>

#define NN   100000
#define NE   1600000
#define INF  256
#define OUTF 64
#define SCAN_B 512
#define NB_SCAN ((NN + SCAN_B - 1) / SCAN_B)   // 196

// ---------------- scratch (device globals; no allocations allowed) ----------
__device__ int   g_deg[NN];
__device__ int   g_rowptr[NN + 1];
__device__ int   g_cursor[NN];
__device__ int2  g_csr[NE];                 // {src, float_as_int(w)}
__device__ int   g_bsum[NB_SCAN];
__device__ int   g_boff[NB_SCAN];
__device__ float g_WT[INF * OUTF];          // W^T  [k][c]
__device__ float g_buf0[(size_t)NN * OUTF];
__device__ float g_buf1[(size_t)NN * OUTF];

// ---------------- CSR build --------------------------------------------------
__global__ void k_zero_deg() {
    int i = blockIdx.x * blockDim.x + threadIdx.x;
    if (i < NN) g_deg[i] = 0;
}

__global__ void k_hist(const int* __restrict__ dst, int E) {
    int e = blockIdx.x * blockDim.x + threadIdx.x;
    if (e < E) atomicAdd(&g_deg[dst[e]], 1);
}

// Phase 1: per-block sums of degrees
__global__ void k_blocksum() {
    __shared__ int red[SCAN_B];
    int t = threadIdx.x;
    int i = blockIdx.x * SCAN_B + t;
    red[t] = (i < NN) ? g_deg[i] : 0;
    __syncthreads();
#pragma unroll
    for (int off = SCAN_B / 2; off > 0; off >>= 1) {
        if (t < off) red[t] += red[t + off];
        __syncthreads();
    }
    if (t == 0) g_bsum[blockIdx.x] = red[0];
}

// Phase 2: single-block scan of the 196 block sums (tiny)
__global__ void k_scanbsum() {
    __shared__ int s[256];
    int t = threadIdx.x;
    int v = (t < NB_SCAN) ? g_bsum[t] : 0;
    s[t] = v;
    __syncthreads();
#pragma unroll
    for (int off = 1; off < 256; off <<= 1) {
        int u = (t >= off) ? s[t - off] : 0;
        __syncthreads();
        s[t] += u;
        __syncthreads();
    }
    if (t < NB_SCAN) g_boff[t] = s[t] - v;      // exclusive
    if (t == NB_SCAN - 1) g_rowptr[NN] = s[t];  // total edge count
}

// Phase 3: per-block local scan + block offset -> rowptr/cursor
__global__ void k_fill() {
    __shared__ int s[SCAN_B];
    int t = threadIdx.x;
    int i = blockIdx.x * SCAN_B + t;
    int v = (i < NN) ? g_deg[i] : 0;
    s[t] = v;
    __syncthreads();
#pragma unroll
    for (int off = 1; off < SCAN_B; off <<= 1) {
        int u = (t >= off) ? s[t - off] : 0;
        __syncthreads();
        s[t] += u;
        __syncthreads();
    }
    if (i < NN) {
        int p = g_boff[blockIdx.x] + s[t] - v;  // exclusive prefix
        g_rowptr[i] = p;
        g_cursor[i] = p;
    }
}

__global__ void k_scatter(const int* __restrict__ src, const int* __restrict__ dst,
                          const float* __restrict__ w, int E) {
    int e = blockIdx.x * blockDim.x + threadIdx.x;
    if (e < E) {
        int d = dst[e];
        int p = atomicAdd(&g_cursor[d], 1);
        g_csr[p] = make_int2(src[e], __float_as_int(w[e]));
    }
}

// ---------------- W transpose ------------------------------------------------
__global__ void k_transpose_w(const float* __restrict__ W) {
    int i = blockIdx.x * blockDim.x + threadIdx.x;   // i = c*256 + k
    if (i < OUTF * INF) {
        int c = i >> 8;
        int k = i & 255;
        g_WT[k * OUTF + c] = W[i];
    }
}

// ---------------- GEMM: out = x @ W^T + b  ->  g_buf0 ------------------------
// block: 128 threads, tile 64 rows x 64 cols, thread tile 4x8
__global__ void k_gemm(const float* __restrict__ x, const float* __restrict__ bias, int M) {
    __shared__ float xs[64 * 64];   // [row][k]
    __shared__ float ws[64 * 64];   // [k][c]
    const int t  = threadIdx.x;
    const int tx = t & 7;           // col group: cols tx*8 .. tx*8+7
    const int ty = t >> 3;          // row group: rows ty*4 .. ty*4+3
    const int m0 = blockIdx.x * 64;

    float acc[4][8];
#pragma unroll
    for (int j = 0; j < 4; ++j)
#pragma unroll
        for (int jj = 0; jj < 8; ++jj) acc[j][jj] = 0.f;

    for (int kb = 0; kb < INF; kb += 64) {
#pragma unroll
        for (int i = 0; i < 8; ++i) {
            int idx = i * 128 + t;       // 0..1023 float4 slots
            int row = idx >> 4;          // 0..63
            int kq  = idx & 15;          // 0..15 (float4 within 64)
            float4 v = make_float4(0.f, 0.f, 0.f, 0.f);
            if (m0 + row < M)
                v = *(const float4*)&x[(size_t)(m0 + row) * INF + kb + kq * 4];
            *(float4*)&xs[row * 64 + kq * 4] = v;
            float4 wv = *(const float4*)&g_WT[(kb + row) * OUTF + kq * 4];
            *(float4*)&ws[row * 64 + kq * 4] = wv;
        }
        __syncthreads();
#pragma unroll
        for (int k = 0; k < 64; ++k) {
            float4 b0 = *(const float4*)&ws[k * 64 + tx * 8];
            float4 b1 = *(const float4*)&ws[k * 64 + tx * 8 + 4];
            float a[4];
#pragma unroll
            for (int j = 0; j < 4; ++j) a[j] = xs[(ty * 4 + j) * 64 + k];
#pragma unroll
            for (int j = 0; j < 4; ++j) {
                acc[j][0] += a[j] * b0.x; acc[j][1] += a[j] * b0.y;
                acc[j][2] += a[j] * b0.z; acc[j][3] += a[j] * b0.w;
                acc[j][4] += a[j] * b1.x; acc[j][5] += a[j] * b1.y;
                acc[j][6] += a[j] * b1.z; acc[j][7] += a[j] * b1.w;
            }
        }
        __syncthreads();
    }

    float4 bb0 = *(const float4*)&bias[tx * 8];
    float4 bb1 = *(const float4*)&bias[tx * 8 + 4];
#pragma unroll
    for (int j = 0; j < 4; ++j) {
        int row = m0 + ty * 4 + j;
        if (row < M) {
            float4 o0 = make_float4(acc[j][0] + bb0.x, acc[j][1] + bb0.y,
                                    acc[j][2] + bb0.z, acc[j][3] + bb0.w);
            float4 o1 = make_float4(acc[j][4] + bb1.x, acc[j][5] + bb1.y,
                                    acc[j][6] + bb1.z, acc[j][7] + bb1.w);
            *(float4*)&g_buf0[(size_t)row * OUTF + tx * 8]     = o0;
            *(float4*)&g_buf0[(size_t)row * OUTF + tx * 8 + 4] = o1;
        }
    }
}

// ---------------- SpMM hop (CSR gather, no float atomics) --------------------
// blockDim = (32, 8): one warp per node, lane f handles features 2f, 2f+1
__global__ void k_spmm(int insel, int outsel, float* __restrict__ dout) {
    const float2* __restrict__ in =
        (insel == 0) ? (const float2*)g_buf0 : (const float2*)g_buf1;
    float2* __restrict__ out =
        (outsel == 0) ? (float2*)g_buf0 :
        (outsel == 1) ? (float2*)g_buf1 : (float2*)dout;

    int node = blockIdx.x * 8 + threadIdx.y;
    if (node >= NN) return;
    int f = threadIdx.x;                  // 0..31
    int beg = g_rowptr[node];
    int end = g_rowptr[node + 1];

    float2 acc = make_float2(0.f, 0.f);
    int e = beg;
    for (; e + 4 <= end; e += 4) {
        int2 c0 = __ldg(&g_csr[e]);
        int2 c1 = __ldg(&g_csr[e + 1]);
        int2 c2 = __ldg(&g_csr[e + 2]);
        int2 c3 = __ldg(&g_csr[e + 3]);
        float2 v0 = __ldg(&in[(size_t)c0.x * 32 + f]);
        float2 v1 = __ldg(&in[(size_t)c1.x * 32 + f]);
        float2 v2 = __ldg(&in[(size_t)c2.x * 32 + f]);
        float2 v3 = __ldg(&in[(size_t)c3.x * 32 + f]);
        float w0 = __int_as_float(c0.y), w1 = __int_as_float(c1.y);
        float w2 = __int_as_float(c2.y), w3 = __int_as_float(c3.y);
        acc.x += w0 * v0.x; acc.y += w0 * v0.y;
        acc.x += w1 * v1.x; acc.y += w1 * v1.y;
        acc.x += w2 * v2.x; acc.y += w2 * v2.y;
        acc.x += w3 * v3.x; acc.y += w3 * v3.y;
    }
    for (; e < end; ++e) {
        int2 c = __ldg(&g_csr[e]);
        float w = __int_as_float(c.y);
        float2 v = __ldg(&in[(size_t)c.x * 32 + f]);
        acc.x += w * v.x; acc.y += w * v.y;
    }
    out[(size_t)node * 32 + f] = acc;
}

// ---------------- launch -----------------------------------------------------
extern "C" void kernel_launch(void* const* d_in, const int* in_sizes, int n_in,
                              void* d_out, int out_size) {
    const float* x    = (const float*)d_in[0];
    const float* W    = (const float*)d_in[1];
    const float* bias = (const float*)d_in[2];
    const int*   esrc = (const int*)d_in[3];
    const int*   edst = (const int*)d_in[4];
    const float* ew   = (const float*)d_in[5];
    float* out = (float*)d_out;

    const int M = in_sizes[0] / INF;      // 100000
    const int E = in_sizes[3];            // 1600000

    // W^T
    k_transpose_w<<<(OUTF * INF + 255) / 256, 256>>>(W);
    // CSR build (by dst)
    k_zero_deg<<<(NN + 255) / 256, 256>>>();
    k_hist<<<(E + 255) / 256, 256>>>(edst, E);
    k_blocksum<<<NB_SCAN, SCAN_B>>>();
    k_scanbsum<<<1, 256>>>();
    k_fill<<<NB_SCAN, SCAN_B>>>();
    k_scatter<<<(E + 255) / 256, 256>>>(esrc, edst, ew, E);
    // GEMM -> buf0
    k_gemm<<<(M + 63) / 64, 128>>>(x, bias, M);
    // 3 hops: buf0 -> buf1 -> buf0 -> d_out
    dim3 bt(32, 8);
    int nblk = (NN + 7) / 8;
    k_spmm<<<nblk, bt>>>(0, 1, out);
    k_spmm<<<nblk, bt>>>(1, 0, out);
    k_spmm<<<nblk, bt>>>(0, 2, out);
    (void)n_in; (void)out_size;
}

// round 9
// speedup vs baseline: 1.8838x; 1.2907x over previous
#include <cuda_runtime.h>
#include <cuda_bf16.h>
#include <stdint.h>

#define NN   100000
#define NE   1600000
#define INF  256
#define OUTF 64
#define SCAN_B 512
#define NB_SCAN ((NN + SCAN_B - 1) / SCAN_B)   // 196
#define TM 128
#define GEMM_THREADS 256
#define NKSTEP (INF / 16)                      // 16

// ---------------- scratch (device globals; no allocations allowed) ----------
__device__ int   g_deg[NN];
__device__ int   g_rowptr[NN + 1];
__device__ int   g_cursor[NN];
__device__ int2  g_csr[NE];                 // {src, float_as_int(w)}
__device__ int   g_bsum[NB_SCAN];
__device__ int   g_boff[NB_SCAN];
// W bf16 hi/lo packed in mma.m16n8k16 B-fragment layout:
// index = (kstep*8 + nblk)*32 + lane ; uint2 = {b0, b1}
__device__ uint2 g_Bh[NKSTEP * 8 * 32];
__device__ uint2 g_Bl[NKSTEP * 8 * 32];
__device__ float g_buf0[(size_t)NN * OUTF];
__device__ float g_buf1[(size_t)NN * OUTF];

// ---------------- CSR build --------------------------------------------------
__global__ void k_zero_deg() {
    int i = blockIdx.x * blockDim.x + threadIdx.x;
    if (i < NN) g_deg[i] = 0;
}

__global__ void k_hist(const int* __restrict__ dst, int E) {
    int e = blockIdx.x * blockDim.x + threadIdx.x;
    if (e < E) atomicAdd(&g_deg[dst[e]], 1);
}

__global__ void k_blocksum() {
    __shared__ int red[SCAN_B];
    int t = threadIdx.x;
    int i = blockIdx.x * SCAN_B + t;
    red[t] = (i < NN) ? g_deg[i] : 0;
    __syncthreads();
#pragma unroll
    for (int off = SCAN_B / 2; off > 0; off >>= 1) {
        if (t < off) red[t] += red[t + off];
        __syncthreads();
    }
    if (t == 0) g_bsum[blockIdx.x] = red[0];
}

__global__ void k_scanbsum() {
    __shared__ int s[256];
    int t = threadIdx.x;
    int v = (t < NB_SCAN) ? g_bsum[t] : 0;
    s[t] = v;
    __syncthreads();
#pragma unroll
    for (int off = 1; off < 256; off <<= 1) {
        int u = (t >= off) ? s[t - off] : 0;
        __syncthreads();
        s[t] += u;
        __syncthreads();
    }
    if (t < NB_SCAN) g_boff[t] = s[t] - v;
    if (t == NB_SCAN - 1) g_rowptr[NN] = s[t];
}

__global__ void k_fill() {
    __shared__ int s[SCAN_B];
    int t = threadIdx.x;
    int i = blockIdx.x * SCAN_B + t;
    int v = (i < NN) ? g_deg[i] : 0;
    s[t] = v;
    __syncthreads();
#pragma unroll
    for (int off = 1; off < SCAN_B; off <<= 1) {
        int u = (t >= off) ? s[t - off] : 0;
        __syncthreads();
        s[t] += u;
        __syncthreads();
    }
    if (i < NN) {
        int p = g_boff[blockIdx.x] + s[t] - v;
        g_rowptr[i] = p;
        g_cursor[i] = p;
    }
}

__global__ void k_scatter(const int* __restrict__ src, const int* __restrict__ dst,
                          const float* __restrict__ w, int E) {
    int e = blockIdx.x * blockDim.x + threadIdx.x;
    if (e < E) {
        int d = dst[e];
        int p = atomicAdd(&g_cursor[d], 1);
        g_csr[p] = make_int2(src[e], __float_as_int(w[e]));
    }
}

// ---------------- helpers ----------------------------------------------------
__device__ __forceinline__ void split_pack(float a, float b, uint32_t& hi, uint32_t& lo) {
    __nv_bfloat16 h0 = __float2bfloat16(a);
    __nv_bfloat16 h1 = __float2bfloat16(b);
    __nv_bfloat16 l0 = __float2bfloat16(a - __bfloat162float(h0));
    __nv_bfloat16 l1 = __float2bfloat16(b - __bfloat162float(h1));
    __nv_bfloat162 hp(h0, h1), lp(l0, l1);
    hi = *(uint32_t*)&hp;
    lo = *(uint32_t*)&lp;
}

__device__ __forceinline__ void hmma(float* c, const uint32_t* a, const uint2 b) {
    asm volatile(
        "mma.sync.aligned.m16n8k16.row.col.f32.bf16.bf16.f32 "
        "{%0,%1,%2,%3}, {%4,%5,%6,%7}, {%8,%9}, {%0,%1,%2,%3};"
        : "+f"(c[0]), "+f"(c[1]), "+f"(c[2]), "+f"(c[3])
        : "r"(a[0]), "r"(a[1]), "r"(a[2]), "r"(a[3]), "r"(b.x), "r"(b.y));
}

// ---------------- W prep: bf16 hi/lo fragment packing ------------------------
// one thread per (kstep, nblk, lane); n = nblk*8 + lane/4, k0 = kstep*16 + (lane%4)*2
__global__ void k_prepB(const float* __restrict__ W) {
    int i = blockIdx.x * blockDim.x + threadIdx.x;
    if (i >= NKSTEP * 8 * 32) return;
    int lane = i & 31;
    int nblk = (i >> 5) & 7;
    int ks   = i >> 8;
    int n  = nblk * 8 + (lane >> 2);
    int k0 = ks * 16 + (lane & 3) * 2;
    const float* wr = W + (size_t)n * INF;
    uint32_t h0, l0, h1, l1;
    split_pack(wr[k0],     wr[k0 + 1], h0, l0);   // b0: k0, k0+1
    split_pack(wr[k0 + 8], wr[k0 + 9], h1, l1);   // b1: k0+8, k0+9
    g_Bh[i] = make_uint2(h0, h1);
    g_Bl[i] = make_uint2(l0, l1);
}

// ---------------- tensor-core GEMM: g_buf0 = x @ W^T + b ---------------------
// CTA: 128 rows x 64 cols. 8 warps: warp_m = wid&3 (rows), warp_n = wid>>2 (cols).
// Warp tile 32x32 = 2 m16 frags x 4 n8 frags. bf16x3 split precision.
__global__ void __launch_bounds__(GEMM_THREADS)
k_gemm_mma(const float* __restrict__ x, const float* __restrict__ bias, int M) {
    const int tid  = threadIdx.x;
    const int wid  = tid >> 5;
    const int lane = tid & 31;
    const int warp_m = wid & 3;
    const int warp_n = wid >> 2;
    const int m0 = blockIdx.x * TM + warp_m * 32;

    const int qr = lane >> 2;          // 0..7 (row within frag)
    const int qc = (lane & 3) * 2;     // 0,2,4,6 (col pair)

    float c[2][4][4];
#pragma unroll
    for (int mf = 0; mf < 2; ++mf)
#pragma unroll
        for (int nf = 0; nf < 4; ++nf)
#pragma unroll
            for (int j = 0; j < 4; ++j) c[mf][nf][j] = 0.f;

    // row pointers (guarded); rows: m0 + mf*16 + qr and +8
    const float* xp[2][2];
    bool vld[2][2];
#pragma unroll
    for (int mf = 0; mf < 2; ++mf)
#pragma unroll
        for (int h = 0; h < 2; ++h) {
            int r = m0 + mf * 16 + h * 8 + qr;
            vld[mf][h] = (r < M);
            xp[mf][h] = x + (size_t)(vld[mf][h] ? r : 0) * INF;
        }

    const int bbase = warp_n * 4;     // nblk offset

    for (int ks = 0; ks < NKSTEP; ++ks) {
        const int k0 = ks * 16 + qc;
        // load + split A fragments
        uint32_t ah[2][4], al[2][4];
#pragma unroll
        for (int mf = 0; mf < 2; ++mf) {
            float2 p00 = vld[mf][0] ? *(const float2*)(xp[mf][0] + k0)     : make_float2(0.f, 0.f);
            float2 p02 = vld[mf][0] ? *(const float2*)(xp[mf][0] + k0 + 8) : make_float2(0.f, 0.f);
            float2 p10 = vld[mf][1] ? *(const float2*)(xp[mf][1] + k0)     : make_float2(0.f, 0.f);
            float2 p12 = vld[mf][1] ? *(const float2*)(xp[mf][1] + k0 + 8) : make_float2(0.f, 0.f);
            split_pack(p00.x, p00.y, ah[mf][0], al[mf][0]);
            split_pack(p10.x, p10.y, ah[mf][1], al[mf][1]);
            split_pack(p02.x, p02.y, ah[mf][2], al[mf][2]);
            split_pack(p12.x, p12.y, ah[mf][3], al[mf][3]);
        }
        // load B fragments
        uint2 bh[4], bl[4];
#pragma unroll
        for (int nf = 0; nf < 4; ++nf) {
            int idx = (ks * 8 + bbase + nf) * 32 + lane;
            bh[nf] = g_Bh[idx];
            bl[nf] = g_Bl[idx];
        }
        // 3-term split-precision MMA
#pragma unroll
        for (int mf = 0; mf < 2; ++mf)
#pragma unroll
            for (int nf = 0; nf < 4; ++nf) {
                hmma(c[mf][nf], ah[mf], bh[nf]);
                hmma(c[mf][nf], ah[mf], bl[nf]);
                hmma(c[mf][nf], al[mf], bh[nf]);
            }
    }

    // epilogue: add bias, store
#pragma unroll
    for (int mf = 0; mf < 2; ++mf) {
        int r0 = m0 + mf * 16 + qr;
#pragma unroll
        for (int nf = 0; nf < 4; ++nf) {
            int col = warp_n * 32 + nf * 8 + qc;
            float bx = __ldg(&bias[col]);
            float by = __ldg(&bias[col + 1]);
            if (r0 < M)
                *(float2*)&g_buf0[(size_t)r0 * OUTF + col] =
                    make_float2(c[mf][nf][0] + bx, c[mf][nf][1] + by);
            if (r0 + 8 < M)
                *(float2*)&g_buf0[(size_t)(r0 + 8) * OUTF + col] =
                    make_float2(c[mf][nf][2] + bx, c[mf][nf][3] + by);
        }
    }
}

// ---------------- SpMM hop (CSR gather, no float atomics) --------------------
__global__ void k_spmm(int insel, int outsel, float* __restrict__ dout) {
    const float2* __restrict__ in =
        (insel == 0) ? (const float2*)g_buf0 : (const float2*)g_buf1;
    float2* __restrict__ out =
        (outsel == 0) ? (float2*)g_buf0 :
        (outsel == 1) ? (float2*)g_buf1 : (float2*)dout;

    int node = blockIdx.x * 8 + threadIdx.y;
    if (node >= NN) return;
    int f = threadIdx.x;
    int beg = g_rowptr[node];
    int end = g_rowptr[node + 1];

    float2 acc = make_float2(0.f, 0.f);
    int e = beg;
    for (; e + 4 <= end; e += 4) {
        int2 c0 = __ldg(&g_csr[e]);
        int2 c1 = __ldg(&g_csr[e + 1]);
        int2 c2 = __ldg(&g_csr[e + 2]);
        int2 c3 = __ldg(&g_csr[e + 3]);
        float2 v0 = __ldg(&in[(size_t)c0.x * 32 + f]);
        float2 v1 = __ldg(&in[(size_t)c1.x * 32 + f]);
        float2 v2 = __ldg(&in[(size_t)c2.x * 32 + f]);
        float2 v3 = __ldg(&in[(size_t)c3.x * 32 + f]);
        float w0 = __int_as_float(c0.y), w1 = __int_as_float(c1.y);
        float w2 = __int_as_float(c2.y), w3 = __int_as_float(c3.y);
        acc.x += w0 * v0.x; acc.y += w0 * v0.y;
        acc.x += w1 * v1.x; acc.y += w1 * v1.y;
        acc.x += w2 * v2.x; acc.y += w2 * v2.y;
        acc.x += w3 * v3.x; acc.y += w3 * v3.y;
    }
    for (; e < end; ++e) {
        int2 c = __ldg(&g_csr[e]);
        float w = __int_as_float(c.y);
        float2 v = __ldg(&in[(size_t)c.x * 32 + f]);
        acc.x += w * v.x; acc.y += w * v.y;
    }
    out[(size_t)node * 32 + f] = acc;
}

// ---------------- launch -----------------------------------------------------
extern "C" void kernel_launch(void* const* d_in, const int* in_sizes, int n_in,
                              void* d_out, int out_size) {
    const float* x    = (const float*)d_in[0];
    const float* W    = (const float*)d_in[1];
    const float* bias = (const float*)d_in[2];
    const int*   esrc = (const int*)d_in[3];
    const int*   edst = (const int*)d_in[4];
    const float* ew   = (const float*)d_in[5];
    float* out = (float*)d_out;

    const int M = in_sizes[0] / INF;      // 100000
    const int E = in_sizes[3];            // 1600000

    // W -> bf16 hi/lo mma fragments
    k_prepB<<<(NKSTEP * 8 * 32 + 255) / 256, 256>>>(W);
    // CSR build (by dst)
    k_zero_deg<<<(NN + 255) / 256, 256>>>();
    k_hist<<<(E + 255) / 256, 256>>>(edst, E);
    k_blocksum<<<NB_SCAN, SCAN_B>>>();
    k_scanbsum<<<1, 256>>>();
    k_fill<<<NB_SCAN, SCAN_B>>>();
    k_scatter<<<(E + 255) / 256, 256>>>(esrc, edst, ew, E);
    // tensor-core GEMM -> buf0
    k_gemm_mma<<<(M + TM - 1) / TM, GEMM_THREADS>>>(x, bias, M);
    // 3 hops: buf0 -> buf1 -> buf0 -> d_out
    dim3 bt(32, 8);
    int nblk = (NN + 7) / 8;
    k_spmm<<<nblk, bt>>>(0, 1, out);
    k_spmm<<<nblk, bt>>>(1, 0, out);
    k_spmm<<<nblk, bt>>>(0, 2, out);
    (void)n_in; (void)out_size;
}

// round 11
// speedup vs baseline: 2.0346x; 1.0801x over previous
#include <cuda_runtime.h>
#include <cuda_bf16.h>
#include <stdint.h>

#define NN   100000
#define NE   1600000
#define INF  256
#define OUTF 64
#define SCAN_B 512
#define NB_SCAN ((NN + SCAN_B - 1) / SCAN_B)   // 196
#define TM 128
#define NKSTEP (INF / 16)                      // 16
#define NGEMMB ((NN + TM - 1) / TM)            // 782
#define NZEROB ((NN + 255) / 256)              // 391
#define NPREPB ((NKSTEP * 8 * 32 + 255) / 256) // 16

// ---------------- scratch (device globals; no allocations allowed) ----------
__device__ int   g_deg[NN];
__device__ int   g_rowptr[NN + 1];
__device__ int   g_cursor[NN];
__device__ int2  g_csr[NE];                 // {src, float_as_int(w)}
__device__ int   g_bsum[NB_SCAN];
// W bf16 hi/lo packed in mma.m16n8k16 B-fragment layout:
// index = (kstep*8 + nblk)*32 + lane ; uint2 = {b0, b1}
__device__ uint2 g_Bh[NKSTEP * 8 * 32];
__device__ uint2 g_Bl[NKSTEP * 8 * 32];
__device__ float g_buf0[(size_t)NN * OUTF];
__device__ float g_buf1[(size_t)NN * OUTF];

// ---------------- helpers ----------------------------------------------------
__device__ __forceinline__ void split_pack(float a, float b, uint32_t& hi, uint32_t& lo) {
    __nv_bfloat16 h0 = __float2bfloat16(a);
    __nv_bfloat16 h1 = __float2bfloat16(b);
    __nv_bfloat16 l0 = __float2bfloat16(a - __bfloat162float(h0));
    __nv_bfloat16 l1 = __float2bfloat16(b - __bfloat162float(h1));
    __nv_bfloat162 hp(h0, h1), lp(l0, l1);
    hi = *(uint32_t*)&hp;
    lo = *(uint32_t*)&lp;
}

__device__ __forceinline__ void hmma(float* c, const uint32_t* a, const uint2 b) {
    asm volatile(
        "mma.sync.aligned.m16n8k16.row.col.f32.bf16.bf16.f32 "
        "{%0,%1,%2,%3}, {%4,%5,%6,%7}, {%8,%9}, {%0,%1,%2,%3};"
        : "+f"(c[0]), "+f"(c[1]), "+f"(c[2]), "+f"(c[3])
        : "r"(a[0]), "r"(a[1]), "r"(a[2]), "r"(a[3]), "r"(b.x), "r"(b.y));
}

// ---------------- init: zero degrees + pack W fragments (fused) --------------
__global__ void k_init(const float* __restrict__ W) {
    int bid = blockIdx.x;
    int tid = threadIdx.x;
    if (bid < NZEROB) {
        int i = bid * 256 + tid;
        if (i < NN) g_deg[i] = 0;
    } else {
        int i = (bid - NZEROB) * 256 + tid;
        if (i >= NKSTEP * 8 * 32) return;
        int lane = i & 31;
        int nblk = (i >> 5) & 7;
        int ks   = i >> 8;
        int n  = nblk * 8 + (lane >> 2);
        int k0 = ks * 16 + (lane & 3) * 2;
        const float* wr = W + (size_t)n * INF;
        uint32_t h0, l0, h1, l1;
        split_pack(wr[k0],     wr[k0 + 1], h0, l0);
        split_pack(wr[k0 + 8], wr[k0 + 9], h1, l1);
        g_Bh[i] = make_uint2(h0, h1);
        g_Bl[i] = make_uint2(l0, l1);
    }
}

// ---------------- CSR build --------------------------------------------------
__global__ void k_hist(const int* __restrict__ dst, int E) {
    int e = blockIdx.x * blockDim.x + threadIdx.x;
    if (e < E) atomicAdd(&g_deg[dst[e]], 1);
}

__global__ void k_blocksum() {
    __shared__ int red[SCAN_B];
    int t = threadIdx.x;
    int i = blockIdx.x * SCAN_B + t;
    red[t] = (i < NN) ? g_deg[i] : 0;
    __syncthreads();
#pragma unroll
    for (int off = SCAN_B / 2; off > 0; off >>= 1) {
        if (t < off) red[t] += red[t + off];
        __syncthreads();
    }
    if (t == 0) g_bsum[blockIdx.x] = red[0];
}

// fill: block offset computed inline from g_bsum (no separate scan kernel)
__global__ void k_fill() {
    __shared__ int s[SCAN_B];
    int t = threadIdx.x;
    int bid = blockIdx.x;
    // block offset = sum of g_bsum[0..bid)
    int part = 0;
    for (int j = t; j < bid; j += SCAN_B) part += g_bsum[j];
    s[t] = part;
    __syncthreads();
#pragma unroll
    for (int off = SCAN_B / 2; off > 0; off >>= 1) {
        if (t < off) s[t] += s[t + off];
        __syncthreads();
    }
    int base = s[0];
    __syncthreads();
    // local inclusive scan of degrees
    int i = bid * SCAN_B + t;
    int v = (i < NN) ? g_deg[i] : 0;
    s[t] = v;
    __syncthreads();
#pragma unroll
    for (int off = 1; off < SCAN_B; off <<= 1) {
        int u = (t >= off) ? s[t - off] : 0;
        __syncthreads();
        s[t] += u;
        __syncthreads();
    }
    if (i < NN) {
        int p = base + s[t] - v;
        g_rowptr[i] = p;
        g_cursor[i] = p;
    }
    if (bid == NB_SCAN - 1 && t == SCAN_B - 1)
        g_rowptr[NN] = base + s[t];
}

// ---------------- fused tensor-core GEMM + edge scatter ----------------------
// blocks [0, NGEMMB): GEMM 128x64 tile (8 warps, bf16x3 split precision)
// blocks [NGEMMB, ...): CSR scatter of one 256-edge chunk
__global__ void __launch_bounds__(256)
k_gemm_scatter(const float* __restrict__ x, const float* __restrict__ bias, int M,
               const int* __restrict__ src, const int* __restrict__ dst,
               const float* __restrict__ w, int E) {
    const int tid  = threadIdx.x;
    if (blockIdx.x >= NGEMMB) {
        int e = (blockIdx.x - NGEMMB) * 256 + tid;
        if (e < E) {
            int d = dst[e];
            int p = atomicAdd(&g_cursor[d], 1);
            g_csr[p] = make_int2(src[e], __float_as_int(w[e]));
        }
        return;
    }

    const int wid  = tid >> 5;
    const int lane = tid & 31;
    const int warp_m = wid & 3;
    const int warp_n = wid >> 2;
    const int m0 = blockIdx.x * TM + warp_m * 32;

    const int qr = lane >> 2;          // 0..7 (row within frag)
    const int qc = (lane & 3) * 2;     // 0,2,4,6 (col pair)

    float c[2][4][4];
#pragma unroll
    for (int mf = 0; mf < 2; ++mf)
#pragma unroll
        for (int nf = 0; nf < 4; ++nf)
#pragma unroll
            for (int j = 0; j < 4; ++j) c[mf][nf][j] = 0.f;

    const float* xp[2][2];
    bool vld[2][2];
#pragma unroll
    for (int mf = 0; mf < 2; ++mf)
#pragma unroll
        for (int h = 0; h < 2; ++h) {
            int r = m0 + mf * 16 + h * 8 + qr;
            vld[mf][h] = (r < M);
            xp[mf][h] = x + (size_t)(vld[mf][h] ? r : 0) * INF;
        }

    const int bbase = warp_n * 4;

    for (int ks = 0; ks < NKSTEP; ++ks) {
        const int k0 = ks * 16 + qc;
        uint32_t ah[2][4], al[2][4];
#pragma unroll
        for (int mf = 0; mf < 2; ++mf) {
            float2 p00 = vld[mf][0] ? *(const float2*)(xp[mf][0] + k0)     : make_float2(0.f, 0.f);
            float2 p02 = vld[mf][0] ? *(const float2*)(xp[mf][0] + k0 + 8) : make_float2(0.f, 0.f);
            float2 p10 = vld[mf][1] ? *(const float2*)(xp[mf][1] + k0)     : make_float2(0.f, 0.f);
            float2 p12 = vld[mf][1] ? *(const float2*)(xp[mf][1] + k0 + 8) : make_float2(0.f, 0.f);
            split_pack(p00.x, p00.y, ah[mf][0], al[mf][0]);
            split_pack(p10.x, p10.y, ah[mf][1], al[mf][1]);
            split_pack(p02.x, p02.y, ah[mf][2], al[mf][2]);
            split_pack(p12.x, p12.y, ah[mf][3], al[mf][3]);
        }
        uint2 bh[4], bl[4];
#pragma unroll
        for (int nf = 0; nf < 4; ++nf) {
            int idx = (ks * 8 + bbase + nf) * 32 + lane;
            bh[nf] = g_Bh[idx];
            bl[nf] = g_Bl[idx];
        }
#pragma unroll
        for (int mf = 0; mf < 2; ++mf)
#pragma unroll
            for (int nf = 0; nf < 4; ++nf) {
                hmma(c[mf][nf], ah[mf], bh[nf]);
                hmma(c[mf][nf], ah[mf], bl[nf]);
                hmma(c[mf][nf], al[mf], bh[nf]);
            }
    }

#pragma unroll
    for (int mf = 0; mf < 2; ++mf) {
        int r0 = m0 + mf * 16 + qr;
#pragma unroll
        for (int nf = 0; nf < 4; ++nf) {
            int col = warp_n * 32 + nf * 8 + qc;
            float bx = __ldg(&bias[col]);
            float by = __ldg(&bias[col + 1]);
            if (r0 < M)
                *(float2*)&g_buf0[(size_t)r0 * OUTF + col] =
                    make_float2(c[mf][nf][0] + bx, c[mf][nf][1] + by);
            if (r0 + 8 < M)
                *(float2*)&g_buf0[(size_t)(r0 + 8) * OUTF + col] =
                    make_float2(c[mf][nf][2] + bx, c[mf][nf][3] + by);
        }
    }
}

// ---------------- SpMM hop (CSR gather, no float atomics) --------------------
// blockDim = (32, 8): one warp per node, lane f handles features 2f, 2f+1
__global__ void k_spmm(int insel, int outsel, float* __restrict__ dout) {
    const float2* __restrict__ in =
        (insel == 0) ? (const float2*)g_buf0 : (const float2*)g_buf1;
    float2* __restrict__ out =
        (outsel == 0) ? (float2*)g_buf0 :
        (outsel == 1) ? (float2*)g_buf1 : (float2*)dout;

    int node = blockIdx.x * 8 + threadIdx.y;
    if (node >= NN) return;
    int f = threadIdx.x;
    int beg = __ldg(&g_rowptr[node]);
    int end = __ldg(&g_rowptr[node + 1]);

    float2 acc = make_float2(0.f, 0.f);
    int e = beg;
    int n8 = beg + ((end - beg) & ~7);
    for (; e < n8; e += 8) {
        int2 cc[8];
#pragma unroll
        for (int j = 0; j < 8; ++j) cc[j] = __ldg(&g_csr[e + j]);
        float2 vv[8];
#pragma unroll
        for (int j = 0; j < 8; ++j) vv[j] = __ldg(&in[(size_t)cc[j].x * 32 + f]);
#pragma unroll
        for (int j = 0; j < 8; ++j) {
            float w = __int_as_float(cc[j].y);
            acc.x += w * vv[j].x;
            acc.y += w * vv[j].y;
        }
    }
    for (; e + 2 <= end; e += 2) {
        int2 c0 = __ldg(&g_csr[e]);
        int2 c1 = __ldg(&g_csr[e + 1]);
        float2 v0 = __ldg(&in[(size_t)c0.x * 32 + f]);
        float2 v1 = __ldg(&in[(size_t)c1.x * 32 + f]);
        float w0 = __int_as_float(c0.y), w1 = __int_as_float(c1.y);
        acc.x += w0 * v0.x; acc.y += w0 * v0.y;
        acc.x += w1 * v1.x; acc.y += w1 * v1.y;
    }
    if (e < end) {
        int2 c0 = __ldg(&g_csr[e]);
        float w = __int_as_float(c0.y);
        float2 v = __ldg(&in[(size_t)c0.x * 32 + f]);
        acc.x += w * v.x; acc.y += w * v.y;
    }
    out[(size_t)node * 32 + f] = acc;
}

// ---------------- launch -----------------------------------------------------
extern "C" void kernel_launch(void* const* d_in, const int* in_sizes, int n_in,
                              void* d_out, int out_size) {
    const float* x    = (const float*)d_in[0];
    const float* W    = (const float*)d_in[1];
    const float* bias = (const float*)d_in[2];
    const int*   esrc = (const int*)d_in[3];
    const int*   edst = (const int*)d_in[4];
    const float* ew   = (const float*)d_in[5];
    float* out = (float*)d_out;

    const int M = in_sizes[0] / INF;      // 100000
    const int E = in_sizes[3];            // 1600000

    // init: zero degrees + pack W fragments
    k_init<<<NZEROB + NPREPB, 256>>>(W);
    // CSR build
    k_hist<<<(E + 255) / 256, 256>>>(edst, E);
    k_blocksum<<<NB_SCAN, SCAN_B>>>();
    k_fill<<<NB_SCAN, SCAN_B>>>();
    // fused GEMM (blocks 0..781) + scatter (rest)
    k_gemm_scatter<<<NGEMMB + (E + 255) / 256, 256>>>(x, bias, M, esrc, edst, ew, E);
    // 3 hops: buf0 -> buf1 -> buf0 -> d_out
    dim3 bt(32, 8);
    int nblk = (NN + 7) / 8;
    k_spmm<<<nblk, bt>>>(0, 1, out);
    k_spmm<<<nblk, bt>>>(1, 0, out);
    k_spmm<<<nblk, bt>>>(0, 2, out);
    (void)n_in; (void)out_size;
}

// round 15
// speedup vs baseline: 2.0908x; 1.0276x over previous
#include <cuda_runtime.h>
#include <cuda_bf16.h>
#include <cuda_fp16.h>
#include <stdint.h>

#define NN   100000
#define NE   1600000
#define INF  256
#define OUTF 64
#define SCAN_B 512
#define NB_SCAN ((NN + SCAN_B - 1) / SCAN_B)   // 196
#define TM 128
#define NKSTEP (INF / 16)                      // 16
#define NGEMMB ((NN + TM - 1) / TM)            // 782
#define NZEROB ((NN + 255) / 256)              // 391
#define NPREPB ((NKSTEP * 8 * 32 + 255) / 256) // 16

// ---------------- scratch (device globals; no allocations allowed) ----------
__device__ int   g_deg[NN];
__device__ int   g_rowptr[NN + 1];
__device__ int   g_cursor[NN];
__device__ int2  g_csr[NE];                 // {src, float_as_int(w)}
__device__ int   g_bsum[NB_SCAN];
// W bf16 hi/lo packed in mma.m16n8k16 B-fragment layout
__device__ uint2 g_Bh[NKSTEP * 8 * 32];
__device__ uint2 g_Bl[NKSTEP * 8 * 32];
// fp16 feature ping-pong buffers: [node][feat-pair] (128B per node row)
__device__ __half2 g_hbuf0[(size_t)NN * 32];
__device__ __half2 g_hbuf1[(size_t)NN * 32];

// ---------------- helpers ----------------------------------------------------
__device__ __forceinline__ void split_pack(float a, float b, uint32_t& hi, uint32_t& lo) {
    __nv_bfloat16 h0 = __float2bfloat16(a);
    __nv_bfloat16 h1 = __float2bfloat16(b);
    __nv_bfloat16 l0 = __float2bfloat16(a - __bfloat162float(h0));
    __nv_bfloat16 l1 = __float2bfloat16(b - __bfloat162float(h1));
    __nv_bfloat162 hp(h0, h1), lp(l0, l1);
    hi = *(uint32_t*)&hp;
    lo = *(uint32_t*)&lp;
}

__device__ __forceinline__ void hmma(float* c, const uint32_t* a, const uint2 b) {
    asm volatile(
        "mma.sync.aligned.m16n8k16.row.col.f32.bf16.bf16.f32 "
        "{%0,%1,%2,%3}, {%4,%5,%6,%7}, {%8,%9}, {%0,%1,%2,%3};"
        : "+f"(c[0]), "+f"(c[1]), "+f"(c[2]), "+f"(c[3])
        : "r"(a[0]), "r"(a[1]), "r"(a[2]), "r"(a[3]), "r"(b.x), "r"(b.y));
}

// ---------------- init: zero degrees + pack W fragments (fused) --------------
__global__ void k_init(const float* __restrict__ W) {
    int bid = blockIdx.x;
    int tid = threadIdx.x;
    if (bid < NZEROB) {
        int i = bid * 256 + tid;
        if (i < NN) g_deg[i] = 0;
    } else {
        int i = (bid - NZEROB) * 256 + tid;
        if (i >= NKSTEP * 8 * 32) return;
        int lane = i & 31;
        int nblk = (i >> 5) & 7;
        int ks   = i >> 8;
        int n  = nblk * 8 + (lane >> 2);
        int k0 = ks * 16 + (lane & 3) * 2;
        const float* wr = W + (size_t)n * INF;
        uint32_t h0, l0, h1, l1;
        split_pack(wr[k0],     wr[k0 + 1], h0, l0);
        split_pack(wr[k0 + 8], wr[k0 + 9], h1, l1);
        g_Bh[i] = make_uint2(h0, h1);
        g_Bl[i] = make_uint2(l0, l1);
    }
}

// ---------------- CSR build --------------------------------------------------
__global__ void k_hist(const int* __restrict__ dst, int E) {
    int e = blockIdx.x * blockDim.x + threadIdx.x;
    if (e < E) atomicAdd(&g_deg[dst[e]], 1);
}

__global__ void k_blocksum() {
    __shared__ int red[SCAN_B];
    int t = threadIdx.x;
    int i = blockIdx.x * SCAN_B + t;
    red[t] = (i < NN) ? g_deg[i] : 0;
    __syncthreads();
#pragma unroll
    for (int off = SCAN_B / 2; off > 0; off >>= 1) {
        if (t < off) red[t] += red[t + off];
        __syncthreads();
    }
    if (t == 0) g_bsum[blockIdx.x] = red[0];
}

__global__ void k_fill() {
    __shared__ int s[SCAN_B];
    int t = threadIdx.x;
    int bid = blockIdx.x;
    int part = 0;
    for (int j = t; j < bid; j += SCAN_B) part += g_bsum[j];
    s[t] = part;
    __syncthreads();
#pragma unroll
    for (int off = SCAN_B / 2; off > 0; off >>= 1) {
        if (t < off) s[t] += s[t + off];
        __syncthreads();
    }
    int base = s[0];
    __syncthreads();
    int i = bid * SCAN_B + t;
    int v = (i < NN) ? g_deg[i] : 0;
    s[t] = v;
    __syncthreads();
#pragma unroll
    for (int off = 1; off < SCAN_B; off <<= 1) {
        int u = (t >= off) ? s[t - off] : 0;
        __syncthreads();
        s[t] += u;
        __syncthreads();
    }
    if (i < NN) {
        int p = base + s[t] - v;
        g_rowptr[i] = p;
        g_cursor[i] = p;
    }
    if (bid == NB_SCAN - 1 && t == SCAN_B - 1)
        g_rowptr[NN] = base + s[t];
}

// ---------------- fused tensor-core GEMM + edge scatter ----------------------
__global__ void __launch_bounds__(256)
k_gemm_scatter(const float* __restrict__ x, const float* __restrict__ bias, int M,
               const int* __restrict__ src, const int* __restrict__ dst,
               const float* __restrict__ w, int E) {
    const int tid  = threadIdx.x;
    if (blockIdx.x >= NGEMMB) {
        int e = (blockIdx.x - NGEMMB) * 256 + tid;
        if (e < E) {
            int d = dst[e];
            int p = atomicAdd(&g_cursor[d], 1);
            g_csr[p] = make_int2(src[e], __float_as_int(w[e]));
        }
        return;
    }

    const int wid  = tid >> 5;
    const int lane = tid & 31;
    const int warp_m = wid & 3;
    const int warp_n = wid >> 2;
    const int m0 = blockIdx.x * TM + warp_m * 32;

    const int qr = lane >> 2;
    const int qc = (lane & 3) * 2;

    float c[2][4][4];
#pragma unroll
    for (int mf = 0; mf < 2; ++mf)
#pragma unroll
        for (int nf = 0; nf < 4; ++nf)
#pragma unroll
            for (int j = 0; j < 4; ++j) c[mf][nf][j] = 0.f;

    const float* xp[2][2];
    bool vld[2][2];
#pragma unroll
    for (int mf = 0; mf < 2; ++mf)
#pragma unroll
        for (int h = 0; h < 2; ++h) {
            int r = m0 + mf * 16 + h * 8 + qr;
            vld[mf][h] = (r < M);
            xp[mf][h] = x + (size_t)(vld[mf][h] ? r : 0) * INF;
        }

    const int bbase = warp_n * 4;

    for (int ks = 0; ks < NKSTEP; ++ks) {
        const int k0 = ks * 16 + qc;
        uint32_t ah[2][4], al[2][4];
#pragma unroll
        for (int mf = 0; mf < 2; ++mf) {
            float2 p00 = vld[mf][0] ? *(const float2*)(xp[mf][0] + k0)     : make_float2(0.f, 0.f);
            float2 p02 = vld[mf][0] ? *(const float2*)(xp[mf][0] + k0 + 8) : make_float2(0.f, 0.f);
            float2 p10 = vld[mf][1] ? *(const float2*)(xp[mf][1] + k0)     : make_float2(0.f, 0.f);
            float2 p12 = vld[mf][1] ? *(const float2*)(xp[mf][1] + k0 + 8) : make_float2(0.f, 0.f);
            split_pack(p00.x, p00.y, ah[mf][0], al[mf][0]);
            split_pack(p10.x, p10.y, ah[mf][1], al[mf][1]);
            split_pack(p02.x, p02.y, ah[mf][2], al[mf][2]);
            split_pack(p12.x, p12.y, ah[mf][3], al[mf][3]);
        }
        uint2 bh[4], bl[4];
#pragma unroll
        for (int nf = 0; nf < 4; ++nf) {
            int idx = (ks * 8 + bbase + nf) * 32 + lane;
            bh[nf] = g_Bh[idx];
            bl[nf] = g_Bl[idx];
        }
#pragma unroll
        for (int mf = 0; mf < 2; ++mf)
#pragma unroll
            for (int nf = 0; nf < 4; ++nf) {
                hmma(c[mf][nf], ah[mf], bh[nf]);
                hmma(c[mf][nf], ah[mf], bl[nf]);
                hmma(c[mf][nf], al[mf], bh[nf]);
            }
    }

    // epilogue: add bias, convert to fp16, store to g_hbuf0
#pragma unroll
    for (int mf = 0; mf < 2; ++mf) {
        int r0 = m0 + mf * 16 + qr;
#pragma unroll
        for (int nf = 0; nf < 4; ++nf) {
            int col = warp_n * 32 + nf * 8 + qc;     // even
            float bx = __ldg(&bias[col]);
            float by = __ldg(&bias[col + 1]);
            if (r0 < M)
                g_hbuf0[(size_t)r0 * 32 + (col >> 1)] =
                    __floats2half2_rn(c[mf][nf][0] + bx, c[mf][nf][1] + by);
            if (r0 + 8 < M)
                g_hbuf0[(size_t)(r0 + 8) * 32 + (col >> 1)] =
                    __floats2half2_rn(c[mf][nf][2] + bx, c[mf][nf][3] + by);
        }
    }
}

// ---------------- SpMM hop (fp16 gather, fp32 accumulate) --------------------
// blockDim = (32, 8): one warp per node, lane f handles features 2f, 2f+1
__global__ void k_spmm(int insel, int outsel, float* __restrict__ dout) {
    const __half2* __restrict__ in = (insel == 0) ? g_hbuf0 : g_hbuf1;

    int node = blockIdx.x * 8 + threadIdx.y;
    if (node >= NN) return;
    int f = threadIdx.x;
    int beg = __ldg(&g_rowptr[node]);
    int end = __ldg(&g_rowptr[node + 1]);

    float2 acc = make_float2(0.f, 0.f);
    int e = beg;
    int n8 = beg + ((end - beg) & ~7);
    for (; e < n8; e += 8) {
        int2 cc[8];
#pragma unroll
        for (int j = 0; j < 8; ++j) cc[j] = __ldg(&g_csr[e + j]);
        __half2 vv[8];
#pragma unroll
        for (int j = 0; j < 8; ++j) vv[j] = __ldg(&in[(size_t)cc[j].x * 32 + f]);
#pragma unroll
        for (int j = 0; j < 8; ++j) {
            float w = __int_as_float(cc[j].y);
            float2 v = __half22float2(vv[j]);
            acc.x += w * v.x;
            acc.y += w * v.y;
        }
    }
    for (; e + 2 <= end; e += 2) {
        int2 c0 = __ldg(&g_csr[e]);
        int2 c1 = __ldg(&g_csr[e + 1]);
        float2 v0 = __half22float2(__ldg(&in[(size_t)c0.x * 32 + f]));
        float2 v1 = __half22float2(__ldg(&in[(size_t)c1.x * 32 + f]));
        float w0 = __int_as_float(c0.y), w1 = __int_as_float(c1.y);
        acc.x += w0 * v0.x; acc.y += w0 * v0.y;
        acc.x += w1 * v1.x; acc.y += w1 * v1.y;
    }
    if (e < end) {
        int2 c0 = __ldg(&g_csr[e]);
        float w = __int_as_float(c0.y);
        float2 v = __half22float2(__ldg(&in[(size_t)c0.x * 32 + f]));
        acc.x += w * v.x; acc.y += w * v.y;
    }

    if (outsel == 2) {
        *(float2*)&dout[(size_t)node * OUTF + f * 2] = acc;
    } else {
        __half2* out = (outsel == 0) ? g_hbuf0 : g_hbuf1;
        out[(size_t)node * 32 + f] = __floats2half2_rn(acc.x, acc.y);
    }
}

// ---------------- launch -----------------------------------------------------
extern "C" void kernel_launch(void* const* d_in, const int* in_sizes, int n_in,
                              void* d_out, int out_size) {
    const float* x    = (const float*)d_in[0];
    const float* W    = (const float*)d_in[1];
    const float* bias = (const float*)d_in[2];
    const int*   esrc = (const int*)d_in[3];
    const int*   edst = (const int*)d_in[4];
    const float* ew   = (const float*)d_in[5];
    float* out = (float*)d_out;

    const int M = in_sizes[0] / INF;      // 100000
    const int E = in_sizes[3];            // 1600000

    // init: zero degrees + pack W fragments
    k_init<<<NZEROB + NPREPB, 256>>>(W);
    // CSR build
    k_hist<<<(E + 255) / 256, 256>>>(edst, E);
    k_blocksum<<<NB_SCAN, SCAN_B>>>();
    k_fill<<<NB_SCAN, SCAN_B>>>();
    // fused GEMM (blocks 0..781) + scatter (rest) -> g_hbuf0
    k_gemm_scatter<<<NGEMMB + (E + 255) / 256, 256>>>(x, bias, M, esrc, edst, ew, E);
    // 3 hops: hbuf0 -> hbuf1 -> hbuf0 -> d_out
    dim3 bt(32, 8);
    int nblk = (NN + 7) / 8;
    k_spmm<<<nblk, bt>>>(0, 1, out);
    k_spmm<<<nblk, bt>>>(1, 0, out);
    k_spmm<<<nblk, bt>>>(0, 2, out);
    (void)n_in; (void)out_size;
}